// round 1
// baseline (speedup 1.0000x reference)
#include <cuda_runtime.h>
#include <math.h>

#define BB  64
#define AA  16
#define CC  512
#define HH  30
#define WW  40
#define HWW 1200
#define EE  256
#define PP  512

// output layout: concat of (aggr_z[B,1,1201], mu[B,1], sigma2[B,1], aggr_x[B,1,1200], x[B,16,1200])
#define OFF_Z  0
#define OFF_MU 76864
#define OFF_S2 76928
#define OFF_AX 76992
#define OFF_X  153792

// scratch (write-before-read every launch -> graph-replay deterministic)
__device__ float g_mean[BB * CC];
__device__ float g_y[BB * AA];
__device__ float g_t1[BB * 48];
__device__ float g_attw[BB * AA];
__device__ float g_aggr[BB * AA * CC];

// ---------------------------------------------------------------------------
// feat_mean[b,c] = mean_hw features[b,c,:]
// grid (64, 128), block 128: warp w handles c = by*4 + w
__global__ void k_mean(const float* __restrict__ F) {
    int b = blockIdx.x;
    int wid = threadIdx.x >> 5, lane = threadIdx.x & 31;
    int c = blockIdx.y * 4 + wid;
    const float* row = F + ((size_t)b * CC + c) * HWW;
    float s = 0.f;
    for (int i = lane; i < HWW; i += 32) s += row[i];
    #pragma unroll
    for (int o = 16; o; o >>= 1) s += __shfl_xor_sync(0xFFFFFFFFu, s, o);
    if (!lane) g_mean[b * CC + c] = s * (1.f / HWW);
}

// ---------------------------------------------------------------------------
// y[b,a] = w_sal2[a,:] . feat_mean[b,:] + b_sal2[a]
__global__ void k_y(const float* __restrict__ w2, const float* __restrict__ b2) {
    int b = blockIdx.x, a = threadIdx.x;
    if (a >= AA) return;
    const float* m = g_mean + b * CC;
    const float* w = w2 + a * CC;
    float s = b2[a];
    for (int c = 0; c < CC; c++) s += w[c] * m[c];
    g_y[b * AA + a] = s;
}

// ---------------------------------------------------------------------------
// x[b,a,hw] = relu(w_sal3[a,:] . F[b,:,hw] + b_sal3[a])  -> out + OFF_X
// grid (64, 5), block 128, each thread computes 16 a's for 2 hw positions
__global__ void __launch_bounds__(128) k_x(const float* __restrict__ F,
                                           const float* __restrict__ w3,
                                           const float* __restrict__ b3,
                                           float* __restrict__ out) {
    __shared__ float ws[CC * AA];  // transposed [c][a]
    int b = blockIdx.x, tid = threadIdx.x;
    for (int i = tid; i < CC * AA; i += 128)
        ws[i] = w3[(i & 15) * CC + (i >> 4)];
    __syncthreads();

    int hw0 = blockIdx.y * 256 + tid;
    int hw1 = hw0 + 128;
    bool v0 = hw0 < HWW, v1 = hw1 < HWW;
    const float* Fb = F + (size_t)b * CC * HWW;

    float acc0[16], acc1[16];
    #pragma unroll
    for (int a = 0; a < 16; a++) { acc0[a] = 0.f; acc1[a] = 0.f; }

    const float4* ws4 = (const float4*)ws;
    for (int c = 0; c < CC; c++) {
        float f0 = v0 ? Fb[c * HWW + hw0] : 0.f;
        float f1 = v1 ? Fb[c * HWW + hw1] : 0.f;
        #pragma unroll
        for (int a4 = 0; a4 < 4; a4++) {
            float4 w = ws4[c * 4 + a4];
            acc0[a4 * 4 + 0] += w.x * f0; acc0[a4 * 4 + 1] += w.y * f0;
            acc0[a4 * 4 + 2] += w.z * f0; acc0[a4 * 4 + 3] += w.w * f0;
            acc1[a4 * 4 + 0] += w.x * f1; acc1[a4 * 4 + 1] += w.y * f1;
            acc1[a4 * 4 + 2] += w.z * f1; acc1[a4 * 4 + 3] += w.w * f1;
        }
    }

    float* X = out + OFF_X + (size_t)b * AA * HWW;
    #pragma unroll
    for (int a = 0; a < 16; a++) {
        float bias = b3[a];
        if (v0) X[a * HWW + hw0] = fmaxf(acc0[a] + bias, 0.f);
        if (v1) X[a * HWW + hw1] = fmaxf(acc1[a] + bias, 0.f);
    }
}

// ---------------------------------------------------------------------------
// aggr[b,a,c] = (1/HW) sum_hw enc[b,c,hw] * x[b,a,hw]
// grid (64, 4), block 128: tile 128c x 16a, thread = 4c x 4a, K chunk = 48
#define KK 48
#define ESTRIDE 132
__global__ void __launch_bounds__(128) k_aggr(const float* __restrict__ Eenc,
                                              const float* __restrict__ out) {
    __shared__ float Esh[KK * ESTRIDE];
    __shared__ float Xsh[KK * 16];
    int b = blockIdx.x;
    int c0 = blockIdx.y * 128;
    int tid = threadIdx.x;
    int tc = tid & 31, ta = tid >> 5;

    const float* Eb = Eenc + ((size_t)b * CC + c0) * HWW;
    const float* Xb = out + OFF_X + (size_t)b * AA * HWW;

    float acc[4][4];
    #pragma unroll
    for (int i = 0; i < 4; i++)
        #pragma unroll
        for (int j = 0; j < 4; j++) acc[i][j] = 0.f;

    for (int chunk = 0; chunk < 25; chunk++) {
        int k0 = chunk * KK;
        // load E tile transposed: row tid, 12 float4s
        const float4* Erow = (const float4*)(Eb + (size_t)tid * HWW + k0);
        #pragma unroll
        for (int q = 0; q < 12; q++) {
            float4 v = Erow[q];
            Esh[(q * 4 + 0) * ESTRIDE + tid] = v.x;
            Esh[(q * 4 + 1) * ESTRIDE + tid] = v.y;
            Esh[(q * 4 + 2) * ESTRIDE + tid] = v.z;
            Esh[(q * 4 + 3) * ESTRIDE + tid] = v.w;
        }
        // load X tile transposed: 16 rows x 12 float4s
        for (int idx = tid; idx < 16 * 12; idx += 128) {
            int a = idx / 12, q = idx % 12;
            float4 v = *(const float4*)(Xb + a * HWW + k0 + q * 4);
            Xsh[(q * 4 + 0) * 16 + a] = v.x;
            Xsh[(q * 4 + 1) * 16 + a] = v.y;
            Xsh[(q * 4 + 2) * 16 + a] = v.z;
            Xsh[(q * 4 + 3) * 16 + a] = v.w;
        }
        __syncthreads();
        #pragma unroll
        for (int k = 0; k < KK; k++) {
            float4 ev = *(const float4*)(Esh + k * ESTRIDE + tc * 4);
            float4 xv = *(const float4*)(Xsh + k * 16 + ta * 4);
            acc[0][0] += xv.x * ev.x; acc[0][1] += xv.x * ev.y;
            acc[0][2] += xv.x * ev.z; acc[0][3] += xv.x * ev.w;
            acc[1][0] += xv.y * ev.x; acc[1][1] += xv.y * ev.y;
            acc[1][2] += xv.y * ev.z; acc[1][3] += xv.y * ev.w;
            acc[2][0] += xv.z * ev.x; acc[2][1] += xv.z * ev.y;
            acc[2][2] += xv.z * ev.z; acc[2][3] += xv.z * ev.w;
            acc[3][0] += xv.w * ev.x; acc[3][1] += xv.w * ev.y;
            acc[3][2] += xv.w * ev.z; acc[3][3] += xv.w * ev.w;
        }
        __syncthreads();
    }

    #pragma unroll
    for (int ia = 0; ia < 4; ia++) {
        float4 st;
        st.x = acc[ia][0] * (1.f / HWW);
        st.y = acc[ia][1] * (1.f / HWW);
        st.z = acc[ia][2] * (1.f / HWW);
        st.w = acc[ia][3] * (1.f / HWW);
        *(float4*)(g_aggr + ((size_t)b * AA + ta * 4 + ia) * CC + c0 + tc * 4) = st;
    }
}

// ---------------------------------------------------------------------------
// drt1: conv 7x7 stride 5 pad 2, 512->1 channels, + relu -> g_t1[b, 6*8]
// grid (64, 48), block 128
__global__ void k_drt1(const float* __restrict__ F, const float* __restrict__ w1,
                       const float* __restrict__ b1) {
    int b = blockIdx.x, pos = blockIdx.y;
    int oh = pos >> 3, ow = pos & 7;
    int ih0 = oh * 5 - 2, iw0 = ow * 5 - 2;
    int tid = threadIdx.x;
    float s = 0.f;
    for (int idx = tid; idx < CC * 49; idx += 128) {
        int c = idx / 49, k = idx % 49;
        int ih = ih0 + k / 7, iw = iw0 + k % 7;
        if (ih >= 0 && ih < HH && iw >= 0 && iw < WW)
            s += F[((size_t)b * CC + c) * HWW + ih * WW + iw] * w1[idx];
    }
    __shared__ float red[128];
    red[tid] = s; __syncthreads();
    for (int o = 64; o; o >>= 1) {
        if (tid < o) red[tid] += red[tid + o];
        __syncthreads();
    }
    if (!tid) g_t1[b * 48 + pos] = fmaxf(red[0] + b1[0], 0.f);
}

// ---------------------------------------------------------------------------
// drt2: full 6x8 conv -> 2 values; mu, sigma2 = exp
// grid 64, block 64 (warp 0 -> mu, warp 1 -> sigma2)
__global__ void k_drt2(const float* __restrict__ w2, const float* __restrict__ b2,
                       float* __restrict__ out) {
    int b = blockIdx.x;
    int o = threadIdx.x >> 5, lane = threadIdx.x & 31;
    float s = 0.f;
    for (int i = lane; i < 48; i += 32) s += g_t1[b * 48 + i] * w2[o * 48 + i];
    #pragma unroll
    for (int sh = 16; sh; sh >>= 1) s += __shfl_xor_sync(0xFFFFFFFFu, s, sh);
    if (!lane) {
        float v = s + b2[o];
        if (o == 0) out[OFF_MU + b] = v;
        else        out[OFF_S2 + b] = expf(v);
    }
}

// ---------------------------------------------------------------------------
// attention scores + softmax -> g_attw[b,a]
// grid 64, block 256 (8 warps)
__global__ void __launch_bounds__(256) k_score(
    const float* __restrict__ subj, const float* __restrict__ wps,
    const float* __restrict__ bps, const float* __restrict__ wpf,
    const float* __restrict__ bpf, const float* __restrict__ watt) {
    __shared__ float ssub[EE];
    __shared__ float ps[PP];
    __shared__ float agg[AA * CC];
    __shared__ float scpart[8][16];
    int b = blockIdx.x, tid = threadIdx.x;
    int wid = tid >> 5, lane = tid & 31;

    for (int i = tid; i < EE; i += 256) ssub[i] = subj[b * EE + i];
    for (int i = tid; i < AA * CC; i += 256) agg[i] = g_aggr[(size_t)b * AA * CC + i];
    __syncthreads();

    // proj_s: warp per p
    for (int p = wid; p < PP; p += 8) {
        const float* w = wps + p * EE;
        float s = 0.f;
        for (int e = lane; e < EE; e += 32) s += w[e] * ssub[e];
        #pragma unroll
        for (int o = 16; o; o >>= 1) s += __shfl_xor_sync(0xFFFFFFFFu, s, o);
        if (!lane) ps[p] = s + bps[p];
    }
    __syncthreads();

    float sc = 0.f;  // lane a (< 16) accumulates score[a]
    const float4* agg4 = (const float4*)agg;
    for (int p = wid; p < PP; p += 8) {
        const float4* w4 = (const float4*)(wpf + p * CC);
        float part[16];
        #pragma unroll
        for (int a = 0; a < 16; a++) part[a] = 0.f;
        #pragma unroll
        for (int j = 0; j < 4; j++) {
            float4 wv = w4[lane + 32 * j];
            #pragma unroll
            for (int a = 0; a < 16; a++) {
                float4 av = agg4[a * 128 + lane + 32 * j];
                part[a] += av.x * wv.x + av.y * wv.y + av.z * wv.z + av.w * wv.w;
            }
        }
        #pragma unroll
        for (int a = 0; a < 16; a++) {
            #pragma unroll
            for (int o = 16; o; o >>= 1)
                part[a] += __shfl_xor_sync(0xFFFFFFFFu, part[a], o);
        }
        if (lane < 16) {
            float mysum = 0.f;
            #pragma unroll
            for (int a = 0; a < 16; a++) if (lane == a) mysum = part[a];
            float th = tanhf(mysum + bpf[p] + ps[p]);
            sc += watt[p] * th;
        }
    }
    if (lane < 16) scpart[wid][lane] = sc;
    __syncthreads();
    if (wid == 0 && lane < 16) {
        float v = 0.f;
        #pragma unroll
        for (int w = 0; w < 8; w++) v += scpart[w][lane];
        // softmax over 16 lanes (b_att is a constant shift -> softmax-invariant)
        float m = v;
        #pragma unroll
        for (int o = 8; o; o >>= 1) m = fmaxf(m, __shfl_xor_sync(0xFFFFu, m, o));
        float e = expf(v - m);
        float sum = e;
        #pragma unroll
        for (int o = 8; o; o >>= 1) sum += __shfl_xor_sync(0xFFFFu, sum, o);
        g_attw[b * AA + lane] = e / sum;
    }
}

// ---------------------------------------------------------------------------
// aggr_x[b,hw] = sum_a x * attw  -> written to AX region AND aggr_z[b,1+hw];
// aggr_z[b,0] = sum_a y * attw
// grid (64, 5), block 256
__global__ void k_final(float* __restrict__ out) {
    __shared__ float aw[16];
    int b = blockIdx.x, tid = threadIdx.x;
    if (tid < 16) aw[tid] = g_attw[b * 16 + tid];
    __syncthreads();
    int hw = blockIdx.y * 256 + tid;
    if (hw < HWW) {
        const float* X = out + OFF_X + (size_t)b * AA * HWW;
        float s = 0.f;
        #pragma unroll
        for (int a = 0; a < 16; a++) s += X[a * HWW + hw] * aw[a];
        out[OFF_AX + b * HWW + hw] = s;
        out[OFF_Z + b * 1201 + 1 + hw] = s;
    }
    if (tid == 0 && blockIdx.y == 0) {
        float z = 0.f;
        #pragma unroll
        for (int a = 0; a < 16; a++) z += g_y[b * 16 + a] * aw[a];
        out[OFF_Z + b * 1201] = z;
    }
}

// ---------------------------------------------------------------------------
extern "C" void kernel_launch(void* const* d_in, const int* in_sizes, int n_in,
                              void* d_out, int out_size) {
    const float* enc  = (const float*)d_in[0];
    const float* feat = (const float*)d_in[1];
    const float* subj = (const float*)d_in[2];
    const float* w2   = (const float*)d_in[3];
    const float* b2   = (const float*)d_in[4];
    const float* w3   = (const float*)d_in[5];
    const float* b3   = (const float*)d_in[6];
    const float* wd1  = (const float*)d_in[7];
    const float* bd1  = (const float*)d_in[8];
    const float* wd2  = (const float*)d_in[9];
    const float* bd2  = (const float*)d_in[10];
    const float* wpf  = (const float*)d_in[11];
    const float* bpf  = (const float*)d_in[12];
    const float* wps  = (const float*)d_in[13];
    const float* bps  = (const float*)d_in[14];
    const float* watt = (const float*)d_in[15];
    float* out = (float*)d_out;

    k_mean<<<dim3(64, 128), 128>>>(feat);
    k_x<<<dim3(64, 5), 128>>>(feat, w3, b3, out);
    k_drt1<<<dim3(64, 48), 128>>>(feat, wd1, bd1);
    k_y<<<64, 32>>>(w2, b2);
    k_drt2<<<64, 64>>>(wd2, bd2, out);
    k_aggr<<<dim3(64, 4), 128>>>(enc, out);
    k_score<<<64, 256>>>(subj, wps, bps, wpf, bpf, watt);
    k_final<<<dim3(64, 5), 256>>>(out);
}

// round 2
// speedup vs baseline: 1.6188x; 1.6188x over previous
#include <cuda_runtime.h>
#include <math.h>

#define BB  64
#define AA  16
#define CC  512
#define HH  30
#define WW  40
#define HWW 1200
#define EE  256
#define PP  512

// output layout: concat of (aggr_z[B,1,1201], mu[B,1], sigma2[B,1], aggr_x[B,1,1200], x[B,16,1200])
#define OFF_Z  0
#define OFF_MU 76864
#define OFF_S2 76928
#define OFF_AX 76992
#define OFF_X  153792

// scratch (zeroed or fully written every launch -> graph-replay deterministic)
__device__ float g_mean[BB * CC];
__device__ float g_y[BB * AA];
__device__ float g_t1[BB * 48];
__device__ float g_score[BB * AA];
__device__ float g_attw[BB * AA];
__device__ float g_aggr[BB * AA * CC];

// ---------------------------------------------------------------------------
// zero the atomic-accumulated scratch. grid 1024, block 512
__global__ void k_zero() {
    int idx = blockIdx.x * 512 + threadIdx.x;   // covers 524288
    g_aggr[idx] = 0.f;
    if (idx < BB * AA) g_score[idx] = 0.f;
}

// ---------------------------------------------------------------------------
// feat_mean[b,c] = mean_hw features[b,c,:]   grid (64,128), block 128
__global__ void k_mean(const float* __restrict__ F) {
    int b = blockIdx.x;
    int wid = threadIdx.x >> 5, lane = threadIdx.x & 31;
    int c = blockIdx.y * 4 + wid;
    const float4* row = (const float4*)(F + ((size_t)b * CC + c) * HWW);
    float s = 0.f;
    for (int i = lane; i < HWW / 4; i += 32) {
        float4 v = row[i];
        s += v.x + v.y + v.z + v.w;
    }
    #pragma unroll
    for (int o = 16; o; o >>= 1) s += __shfl_xor_sync(0xFFFFFFFFu, s, o);
    if (!lane) g_mean[b * CC + c] = s * (1.f / HWW);
}

// ---------------------------------------------------------------------------
// y[b,a] = w_sal2[a,:] . feat_mean[b,:] + b_sal2[a]   grid 64, block 512
__global__ void k_y(const float* __restrict__ w2, const float* __restrict__ b2) {
    int b = blockIdx.x;
    int a = threadIdx.x >> 5, lane = threadIdx.x & 31;
    const float4* m4 = (const float4*)(g_mean + b * CC);
    const float4* w4 = (const float4*)(w2 + a * CC);
    float s = 0.f;
    #pragma unroll
    for (int i = 0; i < 4; i++) {
        float4 mv = m4[lane + 32 * i];
        float4 wv = w4[lane + 32 * i];
        s += mv.x * wv.x + mv.y * wv.y + mv.z * wv.z + mv.w * wv.w;
    }
    #pragma unroll
    for (int o = 16; o; o >>= 1) s += __shfl_xor_sync(0xFFFFFFFFu, s, o);
    if (!lane) g_y[b * AA + a] = s + b2[a];
}

// ---------------------------------------------------------------------------
// x[b,a,hw] = relu(w_sal3[a,:] . F[b,:,hw] + b_sal3[a])
// grid (64, 10), block 128: one hw per thread, 16 a's in registers
__global__ void __launch_bounds__(128) k_x(const float* __restrict__ F,
                                           const float* __restrict__ w3,
                                           const float* __restrict__ b3,
                                           float* __restrict__ out) {
    __shared__ float ws[CC * AA];  // transposed [c][a]
    int b = blockIdx.x, tid = threadIdx.x;
    for (int i = tid; i < CC * AA; i += 128)
        ws[i] = w3[(i & 15) * CC + (i >> 4)];
    __syncthreads();

    int hw = blockIdx.y * 128 + tid;
    bool v = hw < HWW;
    int hwl = v ? hw : 0;
    const float* Fb = F + (size_t)b * CC * HWW + hwl;

    float acc[16];
    #pragma unroll
    for (int a = 0; a < 16; a++) acc[a] = 0.f;

    const float4* ws4 = (const float4*)ws;
    #pragma unroll 4
    for (int c = 0; c < CC; c++) {
        float f = Fb[c * HWW];
        #pragma unroll
        for (int a4 = 0; a4 < 4; a4++) {
            float4 w = ws4[c * 4 + a4];
            acc[a4 * 4 + 0] += w.x * f; acc[a4 * 4 + 1] += w.y * f;
            acc[a4 * 4 + 2] += w.z * f; acc[a4 * 4 + 3] += w.w * f;
        }
    }

    if (v) {
        float* X = out + OFF_X + (size_t)b * AA * HWW + hw;
        #pragma unroll
        for (int a = 0; a < 16; a++)
            X[a * HWW] = fmaxf(acc[a] + b3[a], 0.f);
    }
}

// ---------------------------------------------------------------------------
// aggr[b,a,c] = (1/HW) sum_hw enc[b,c,hw] * x[b,a,hw]
// grid (64, 4, 5): split-K (5 splits of 5 chunks x 48), atomicAdd epilogue
#define KK 48
#define ESTRIDE 132
__global__ void __launch_bounds__(128) k_aggr(const float* __restrict__ Eenc,
                                              const float* __restrict__ out) {
    __shared__ float Esh[KK * ESTRIDE];
    __shared__ float Xsh[KK * 16];
    int b = blockIdx.x;
    int c0 = blockIdx.y * 128;
    int chunk0 = blockIdx.z * 5;
    int tid = threadIdx.x;
    int tc = tid & 31, ta = tid >> 5;

    const float* Eb = Eenc + ((size_t)b * CC + c0) * HWW;
    const float* Xb = out + OFF_X + (size_t)b * AA * HWW;

    float acc[4][4];
    #pragma unroll
    for (int i = 0; i < 4; i++)
        #pragma unroll
        for (int j = 0; j < 4; j++) acc[i][j] = 0.f;

    for (int chunk = chunk0; chunk < chunk0 + 5; chunk++) {
        int k0 = chunk * KK;
        const float4* Erow = (const float4*)(Eb + (size_t)tid * HWW + k0);
        #pragma unroll
        for (int q = 0; q < 12; q++) {
            float4 v = Erow[q];
            Esh[(q * 4 + 0) * ESTRIDE + tid] = v.x;
            Esh[(q * 4 + 1) * ESTRIDE + tid] = v.y;
            Esh[(q * 4 + 2) * ESTRIDE + tid] = v.z;
            Esh[(q * 4 + 3) * ESTRIDE + tid] = v.w;
        }
        for (int idx = tid; idx < 16 * 12; idx += 128) {
            int a = idx / 12, q = idx % 12;
            float4 v = *(const float4*)(Xb + a * HWW + k0 + q * 4);
            Xsh[(q * 4 + 0) * 16 + a] = v.x;
            Xsh[(q * 4 + 1) * 16 + a] = v.y;
            Xsh[(q * 4 + 2) * 16 + a] = v.z;
            Xsh[(q * 4 + 3) * 16 + a] = v.w;
        }
        __syncthreads();
        #pragma unroll
        for (int k = 0; k < KK; k++) {
            float4 ev = *(const float4*)(Esh + k * ESTRIDE + tc * 4);
            float4 xv = *(const float4*)(Xsh + k * 16 + ta * 4);
            acc[0][0] += xv.x * ev.x; acc[0][1] += xv.x * ev.y;
            acc[0][2] += xv.x * ev.z; acc[0][3] += xv.x * ev.w;
            acc[1][0] += xv.y * ev.x; acc[1][1] += xv.y * ev.y;
            acc[1][2] += xv.y * ev.z; acc[1][3] += xv.y * ev.w;
            acc[2][0] += xv.z * ev.x; acc[2][1] += xv.z * ev.y;
            acc[2][2] += xv.z * ev.z; acc[2][3] += xv.z * ev.w;
            acc[3][0] += xv.w * ev.x; acc[3][1] += xv.w * ev.y;
            acc[3][2] += xv.w * ev.z; acc[3][3] += xv.w * ev.w;
        }
        __syncthreads();
    }

    #pragma unroll
    for (int ia = 0; ia < 4; ia++) {
        float* dst = g_aggr + ((size_t)b * AA + ta * 4 + ia) * CC + c0 + tc * 4;
        #pragma unroll
        for (int j = 0; j < 4; j++)
            atomicAdd(dst + j, acc[ia][j] * (1.f / HWW));
    }
}

// ---------------------------------------------------------------------------
// drt1: conv 7x7 stride 5 pad 2, 512->1, + bias + relu -> g_t1[b, 48]
// grid (64, 48), block 128
__global__ void k_drt1(const float* __restrict__ F, const float* __restrict__ w1,
                       const float* __restrict__ b1) {
    int b = blockIdx.x, pos = blockIdx.y;
    int oh = pos >> 3, ow = pos & 7;
    int ih0 = oh * 5 - 2, iw0 = ow * 5 - 2;  // right/bottom halo never OOB
    int tid = threadIdx.x;
    float s = 0.f;
    for (int idx = tid; idx < CC * 7; idx += 128) {
        int c = idx / 7, kh = idx - c * 7;
        int ih = ih0 + kh;
        if (ih < 0) continue;              // ih <= 29 always
        const float* Frow = F + ((size_t)b * CC + c) * HWW + ih * WW;
        const float* wrow = w1 + c * 49 + kh * 7;
        #pragma unroll
        for (int kw = 0; kw < 7; kw++) {
            int iw = iw0 + kw;
            if (iw >= 0) s += Frow[iw] * wrow[kw];   // iw <= 39 always
        }
    }
    __shared__ float red[4];
    int wid = tid >> 5, lane = tid & 31;
    #pragma unroll
    for (int o = 16; o; o >>= 1) s += __shfl_xor_sync(0xFFFFFFFFu, s, o);
    if (!lane) red[wid] = s;
    __syncthreads();
    if (!tid) {
        float t = red[0] + red[1] + red[2] + red[3];
        g_t1[b * 48 + pos] = fmaxf(t + b1[0], 0.f);
    }
}

// ---------------------------------------------------------------------------
// drt2: full 6x8 conv -> 2 values; mu, sigma2 = exp    grid 64, block 64
__global__ void k_drt2(const float* __restrict__ w2, const float* __restrict__ b2,
                       float* __restrict__ out) {
    int b = blockIdx.x;
    int o = threadIdx.x >> 5, lane = threadIdx.x & 31;
    float s = 0.f;
    for (int i = lane; i < 48; i += 32) s += g_t1[b * 48 + i] * w2[o * 48 + i];
    #pragma unroll
    for (int sh = 16; sh; sh >>= 1) s += __shfl_xor_sync(0xFFFFFFFFu, s, sh);
    if (!lane) {
        float v = s + b2[o];
        if (o == 0) out[OFF_MU + b] = v;
        else        out[OFF_S2 + b] = expf(v);
    }
}

// ---------------------------------------------------------------------------
// partial attention scores: grid (64, 8), block 256, 64 p's per block
__global__ void __launch_bounds__(256) k_score(
    const float* __restrict__ subj, const float* __restrict__ wps,
    const float* __restrict__ bps, const float* __restrict__ wpf,
    const float* __restrict__ bpf, const float* __restrict__ watt) {
    __shared__ float ssub[EE];
    __shared__ float ps[64];
    __shared__ float agg[AA * CC];
    int b = blockIdx.x, p0 = blockIdx.y * 64;
    int tid = threadIdx.x;
    int wid = tid >> 5, lane = tid & 31;

    for (int i = tid; i < EE; i += 256) ssub[i] = subj[b * EE + i];
    for (int i = tid; i < AA * CC; i += 256) agg[i] = g_aggr[(size_t)b * AA * CC + i];
    __syncthreads();

    // proj_s for this block's p-chunk
    for (int pi = wid; pi < 64; pi += 8) {
        int p = p0 + pi;
        const float4* w4 = (const float4*)(wps + p * EE);
        const float4* s4 = (const float4*)ssub;
        float s = 0.f;
        #pragma unroll
        for (int i = 0; i < 2; i++) {
            float4 wv = w4[lane + 32 * i], sv = s4[lane + 32 * i];
            s += wv.x * sv.x + wv.y * sv.y + wv.z * sv.z + wv.w * sv.w;
        }
        #pragma unroll
        for (int o = 16; o; o >>= 1) s += __shfl_xor_sync(0xFFFFFFFFu, s, o);
        if (!lane) ps[pi] = s + bps[p];
    }
    __syncthreads();

    float sc = 0.f;
    const float4* agg4 = (const float4*)agg;
    for (int pi = wid; pi < 64; pi += 8) {
        int p = p0 + pi;
        const float4* w4 = (const float4*)(wpf + p * CC);
        float part[16];
        #pragma unroll
        for (int a = 0; a < 16; a++) part[a] = 0.f;
        #pragma unroll
        for (int j = 0; j < 4; j++) {
            float4 wv = w4[lane + 32 * j];
            #pragma unroll
            for (int a = 0; a < 16; a++) {
                float4 av = agg4[a * 128 + lane + 32 * j];
                part[a] += av.x * wv.x + av.y * wv.y + av.z * wv.z + av.w * wv.w;
            }
        }
        #pragma unroll
        for (int a = 0; a < 16; a++) {
            #pragma unroll
            for (int o = 16; o; o >>= 1)
                part[a] += __shfl_xor_sync(0xFFFFFFFFu, part[a], o);
        }
        if (lane < 16) {
            float mysum = 0.f;
            #pragma unroll
            for (int a = 0; a < 16; a++) if (lane == a) mysum = part[a];
            sc += watt[p] * tanhf(mysum + bpf[p] + ps[pi]);
        }
    }
    if (lane < 16) atomicAdd(&g_score[b * AA + lane], sc);
}

// ---------------------------------------------------------------------------
// softmax over 16 scores per batch -> g_attw     grid 64, block 32
__global__ void k_soft() {
    int b = blockIdx.x, lane = threadIdx.x;
    if (lane >= 16) return;
    float v = g_score[b * AA + lane];
    float m = v;
    #pragma unroll
    for (int o = 8; o; o >>= 1) m = fmaxf(m, __shfl_xor_sync(0xFFFFu, m, o));
    float e = expf(v - m);
    float sum = e;
    #pragma unroll
    for (int o = 8; o; o >>= 1) sum += __shfl_xor_sync(0xFFFFu, sum, o);
    g_attw[b * AA + lane] = e / sum;
}

// ---------------------------------------------------------------------------
// aggr_x / aggr_z    grid (64, 5), block 256
__global__ void k_final(float* __restrict__ out) {
    __shared__ float aw[16];
    int b = blockIdx.x, tid = threadIdx.x;
    if (tid < 16) aw[tid] = g_attw[b * 16 + tid];
    __syncthreads();
    int hw = blockIdx.y * 256 + tid;
    if (hw < HWW) {
        const float* X = out + OFF_X + (size_t)b * AA * HWW;
        float s = 0.f;
        #pragma unroll
        for (int a = 0; a < 16; a++) s += X[a * HWW + hw] * aw[a];
        out[OFF_AX + b * HWW + hw] = s;
        out[OFF_Z + b * 1201 + 1 + hw] = s;
    }
    if (tid == 0 && blockIdx.y == 0) {
        float z = 0.f;
        #pragma unroll
        for (int a = 0; a < 16; a++) z += g_y[b * 16 + a] * aw[a];
        out[OFF_Z + b * 1201] = z;
    }
}

// ---------------------------------------------------------------------------
extern "C" void kernel_launch(void* const* d_in, const int* in_sizes, int n_in,
                              void* d_out, int out_size) {
    const float* enc  = (const float*)d_in[0];
    const float* feat = (const float*)d_in[1];
    const float* subj = (const float*)d_in[2];
    const float* w2   = (const float*)d_in[3];
    const float* b2   = (const float*)d_in[4];
    const float* w3   = (const float*)d_in[5];
    const float* b3   = (const float*)d_in[6];
    const float* wd1  = (const float*)d_in[7];
    const float* bd1  = (const float*)d_in[8];
    const float* wd2  = (const float*)d_in[9];
    const float* bd2  = (const float*)d_in[10];
    const float* wpf  = (const float*)d_in[11];
    const float* bpf  = (const float*)d_in[12];
    const float* wps  = (const float*)d_in[13];
    const float* bps  = (const float*)d_in[14];
    const float* watt = (const float*)d_in[15];
    float* out = (float*)d_out;

    k_zero<<<1024, 512>>>();
    k_mean<<<dim3(64, 128), 128>>>(feat);
    k_x<<<dim3(64, 10), 128>>>(feat, w3, b3, out);
    k_drt1<<<dim3(64, 48), 128>>>(feat, wd1, bd1);
    k_y<<<64, 512>>>(w2, b2);
    k_drt2<<<64, 64>>>(wd2, bd2, out);
    k_aggr<<<dim3(64, 4, 5), 128>>>(enc, out);
    k_score<<<dim3(64, 8), 256>>>(subj, wps, bps, wpf, bpf, watt);
    k_soft<<<64, 32>>>();
    k_final<<<dim3(64, 5), 256>>>(out);
}

// round 3
// speedup vs baseline: 1.9989x; 1.2348x over previous
#include <cuda_runtime.h>
#include <math.h>

#define BB  64
#define AA  16
#define CC  512
#define HH  30
#define WW  40
#define HWW 1200
#define EE  256
#define PP  512

#define OFF_Z  0
#define OFF_MU 76864
#define OFF_S2 76928
#define OFF_AX 76992
#define OFF_X  153792

__device__ float g_mean[BB * CC];
__device__ float g_y[BB * AA];
__device__ float g_t1[BB * 48];
__device__ float g_score[BB * AA];
__device__ float g_attw[BB * AA];
__device__ float g_aggr[BB * AA * CC];

// ---------------------------------------------------------------------------
__global__ void k_zero() {
    int idx = blockIdx.x * 512 + threadIdx.x;
    g_aggr[idx] = 0.f;
    if (idx < BB * AA) g_score[idx] = 0.f;
    if (idx < BB * 48) g_t1[idx] = 0.f;
}

// ---------------------------------------------------------------------------
// Fused drt1 conv (raw accum, bias+relu deferred to k_drt2) + per-channel mean.
// grid (64, 8), block 384
__global__ void __launch_bounds__(384) k_drt1f(const float* __restrict__ F,
                                               const float* __restrict__ w1) {
    __shared__ float ch[2][HWW];
    __shared__ float wsh[64 * 49];
    __shared__ float csum[2][12];
    __shared__ float pos_acc[336];

    int b = blockIdx.x, c0 = blockIdx.y * 64;
    int tid = threadIdx.x;
    int wid = tid >> 5, lane = tid & 31;

    for (int i = tid; i < 64 * 49; i += 384) wsh[i] = w1[c0 * 49 + i];

    int pos = tid / 7, kh = tid - pos * 7;
    bool active = tid < 336;
    int oh = pos >> 3, ow = pos & 7;
    int ih = oh * 5 - 2 + kh;
    int iw0 = ow * 5 - 2;
    bool ihok = active && ih >= 0;

    const float* Fb = F + ((size_t)b * CC + c0) * HWW;

    {
        float ps = 0.f;
        if (tid < 300) {
            float4 v = ((const float4*)Fb)[tid];
            ((float4*)ch[0])[tid] = v;
            ps = v.x + v.y + v.z + v.w;
        }
        #pragma unroll
        for (int o = 16; o; o >>= 1) ps += __shfl_xor_sync(0xFFFFFFFFu, ps, o);
        if (!lane) csum[0][wid] = ps;
    }
    __syncthreads();

    float acc = 0.f;
    for (int c = 0; c < 64; c++) {
        int cur = c & 1;
        if (c < 63) {
            float ps = 0.f;
            if (tid < 300) {
                float4 v = ((const float4*)(Fb + (size_t)(c + 1) * HWW))[tid];
                ((float4*)ch[cur ^ 1])[tid] = v;
                ps = v.x + v.y + v.z + v.w;
            }
            #pragma unroll
            for (int o = 16; o; o >>= 1) ps += __shfl_xor_sync(0xFFFFFFFFu, ps, o);
            if (!lane) csum[cur ^ 1][wid] = ps;
        }
        if (tid == 0) {
            float m = 0.f;
            #pragma unroll
            for (int w = 0; w < 12; w++) m += csum[cur][w];
            g_mean[b * CC + c0 + c] = m * (1.f / HWW);
        }
        if (ihok) {
            const float* row = ch[cur] + ih * WW;
            const float* wr = wsh + c * 49 + kh * 7;
            #pragma unroll
            for (int kw = 0; kw < 7; kw++) {
                int iw = iw0 + kw;
                if (iw >= 0) acc += row[iw] * wr[kw];
            }
        }
        __syncthreads();
    }

    if (active) pos_acc[tid] = acc;
    __syncthreads();
    if (active && kh == 0) {
        float s = pos_acc[tid] + pos_acc[tid + 1] + pos_acc[tid + 2]
                + pos_acc[tid + 3] + pos_acc[tid + 4] + pos_acc[tid + 5]
                + pos_acc[tid + 6];
        atomicAdd(&g_t1[b * 48 + pos], s);
    }
}

// ---------------------------------------------------------------------------
__global__ void k_y(const float* __restrict__ w2, const float* __restrict__ b2) {
    int b = blockIdx.x;
    int a = threadIdx.x >> 5, lane = threadIdx.x & 31;
    const float4* m4 = (const float4*)(g_mean + b * CC);
    const float4* w4 = (const float4*)(w2 + a * CC);
    float s = 0.f;
    #pragma unroll
    for (int i = 0; i < 4; i++) {
        float4 mv = m4[lane + 32 * i];
        float4 wv = w4[lane + 32 * i];
        s += mv.x * wv.x + mv.y * wv.y + mv.z * wv.z + mv.w * wv.w;
    }
    #pragma unroll
    for (int o = 16; o; o >>= 1) s += __shfl_xor_sync(0xFFFFFFFFu, s, o);
    if (!lane) g_y[b * AA + a] = s + b2[a];
}

// ---------------------------------------------------------------------------
__global__ void __launch_bounds__(128) k_x(const float* __restrict__ F,
                                           const float* __restrict__ w3,
                                           const float* __restrict__ b3,
                                           float* __restrict__ out) {
    __shared__ float ws[CC * AA];
    int b = blockIdx.x, tid = threadIdx.x;
    for (int i = tid; i < CC * AA; i += 128)
        ws[i] = w3[(i & 15) * CC + (i >> 4)];
    __syncthreads();

    int hw = blockIdx.y * 128 + tid;
    bool v = hw < HWW;
    int hwl = v ? hw : 0;
    const float* Fb = F + (size_t)b * CC * HWW + hwl;

    float acc[16];
    #pragma unroll
    for (int a = 0; a < 16; a++) acc[a] = 0.f;

    const float4* ws4 = (const float4*)ws;
    #pragma unroll 4
    for (int c = 0; c < CC; c++) {
        float f = Fb[c * HWW];
        #pragma unroll
        for (int a4 = 0; a4 < 4; a4++) {
            float4 w = ws4[c * 4 + a4];
            acc[a4 * 4 + 0] += w.x * f; acc[a4 * 4 + 1] += w.y * f;
            acc[a4 * 4 + 2] += w.z * f; acc[a4 * 4 + 3] += w.w * f;
        }
    }

    if (v) {
        float* X = out + OFF_X + (size_t)b * AA * HWW + hw;
        #pragma unroll
        for (int a = 0; a < 16; a++)
            X[a * HWW] = fmaxf(acc[a] + b3[a], 0.f);
    }
}

// ---------------------------------------------------------------------------
#define KK 48
#define ESTRIDE 132
__global__ void __launch_bounds__(128) k_aggr(const float* __restrict__ Eenc,
                                              const float* __restrict__ out) {
    __shared__ float Esh[KK * ESTRIDE];
    __shared__ float Xsh[KK * 16];
    int b = blockIdx.x;
    int c0 = blockIdx.y * 128;
    int chunk0 = blockIdx.z * 5;
    int tid = threadIdx.x;
    int tc = tid & 31, ta = tid >> 5;

    const float* Eb = Eenc + ((size_t)b * CC + c0) * HWW;
    const float* Xb = out + OFF_X + (size_t)b * AA * HWW;

    float acc[4][4];
    #pragma unroll
    for (int i = 0; i < 4; i++)
        #pragma unroll
        for (int j = 0; j < 4; j++) acc[i][j] = 0.f;

    for (int chunk = chunk0; chunk < chunk0 + 5; chunk++) {
        int k0 = chunk * KK;
        const float4* Erow = (const float4*)(Eb + (size_t)tid * HWW + k0);
        #pragma unroll
        for (int q = 0; q < 12; q++) {
            float4 v = Erow[q];
            Esh[(q * 4 + 0) * ESTRIDE + tid] = v.x;
            Esh[(q * 4 + 1) * ESTRIDE + tid] = v.y;
            Esh[(q * 4 + 2) * ESTRIDE + tid] = v.z;
            Esh[(q * 4 + 3) * ESTRIDE + tid] = v.w;
        }
        for (int idx = tid; idx < 16 * 12; idx += 128) {
            int a = idx / 12, q = idx % 12;
            float4 v = *(const float4*)(Xb + a * HWW + k0 + q * 4);
            Xsh[(q * 4 + 0) * 16 + a] = v.x;
            Xsh[(q * 4 + 1) * 16 + a] = v.y;
            Xsh[(q * 4 + 2) * 16 + a] = v.z;
            Xsh[(q * 4 + 3) * 16 + a] = v.w;
        }
        __syncthreads();
        #pragma unroll
        for (int k = 0; k < KK; k++) {
            float4 ev = *(const float4*)(Esh + k * ESTRIDE + tc * 4);
            float4 xv = *(const float4*)(Xsh + k * 16 + ta * 4);
            acc[0][0] += xv.x * ev.x; acc[0][1] += xv.x * ev.y;
            acc[0][2] += xv.x * ev.z; acc[0][3] += xv.x * ev.w;
            acc[1][0] += xv.y * ev.x; acc[1][1] += xv.y * ev.y;
            acc[1][2] += xv.y * ev.z; acc[1][3] += xv.y * ev.w;
            acc[2][0] += xv.z * ev.x; acc[2][1] += xv.z * ev.y;
            acc[2][2] += xv.z * ev.z; acc[2][3] += xv.z * ev.w;
            acc[3][0] += xv.w * ev.x; acc[3][1] += xv.w * ev.y;
            acc[3][2] += xv.w * ev.z; acc[3][3] += xv.w * ev.w;
        }
        __syncthreads();
    }

    #pragma unroll
    for (int ia = 0; ia < 4; ia++) {
        float* dst = g_aggr + ((size_t)b * AA + ta * 4 + ia) * CC + c0 + tc * 4;
        #pragma unroll
        for (int j = 0; j < 4; j++)
            atomicAdd(dst + j, acc[ia][j] * (1.f / HWW));
    }
}

// ---------------------------------------------------------------------------
// drt2: applies drt1 bias+relu, then full 6x8 conv -> mu / sigma2
__global__ void k_drt2(const float* __restrict__ w2, const float* __restrict__ b2,
                       const float* __restrict__ b1, float* __restrict__ out) {
    int b = blockIdx.x;
    int o = threadIdx.x >> 5, lane = threadIdx.x & 31;
    float bias1 = b1[0];
    float s = 0.f;
    for (int i = lane; i < 48; i += 32)
        s += fmaxf(g_t1[b * 48 + i] + bias1, 0.f) * w2[o * 48 + i];
    #pragma unroll
    for (int sh = 16; sh; sh >>= 1) s += __shfl_xor_sync(0xFFFFFFFFu, s, sh);
    if (!lane) {
        float v = s + b2[o];
        if (o == 0) out[OFF_MU + b] = v;
        else        out[OFF_S2 + b] = expf(v);
    }
}

// ---------------------------------------------------------------------------
__global__ void __launch_bounds__(256) k_score(
    const float* __restrict__ subj, const float* __restrict__ wps,
    const float* __restrict__ bps, const float* __restrict__ wpf,
    const float* __restrict__ bpf, const float* __restrict__ watt) {
    __shared__ float ssub[EE];
    __shared__ float ps[64];
    __shared__ float agg[AA * CC];
    int b = blockIdx.x, p0 = blockIdx.y * 64;
    int tid = threadIdx.x;
    int wid = tid >> 5, lane = tid & 31;

    for (int i = tid; i < EE; i += 256) ssub[i] = subj[b * EE + i];
    for (int i = tid; i < AA * CC; i += 256) agg[i] = g_aggr[(size_t)b * AA * CC + i];
    __syncthreads();

    for (int pi = wid; pi < 64; pi += 8) {
        int p = p0 + pi;
        const float4* w4 = (const float4*)(wps + p * EE);
        const float4* s4 = (const float4*)ssub;
        float s = 0.f;
        #pragma unroll
        for (int i = 0; i < 2; i++) {
            float4 wv = w4[lane + 32 * i], sv = s4[lane + 32 * i];
            s += wv.x * sv.x + wv.y * sv.y + wv.z * sv.z + wv.w * sv.w;
        }
        #pragma unroll
        for (int o = 16; o; o >>= 1) s += __shfl_xor_sync(0xFFFFFFFFu, s, o);
        if (!lane) ps[pi] = s + bps[p];
    }
    __syncthreads();

    float sc = 0.f;
    const float4* agg4 = (const float4*)agg;
    for (int pi = wid; pi < 64; pi += 8) {
        int p = p0 + pi;
        const float4* w4 = (const float4*)(wpf + p * CC);
        float part[16];
        #pragma unroll
        for (int a = 0; a < 16; a++) part[a] = 0.f;
        #pragma unroll
        for (int j = 0; j < 4; j++) {
            float4 wv = w4[lane + 32 * j];
            #pragma unroll
            for (int a = 0; a < 16; a++) {
                float4 av = agg4[a * 128 + lane + 32 * j];
                part[a] += av.x * wv.x + av.y * wv.y + av.z * wv.z + av.w * wv.w;
            }
        }
        #pragma unroll
        for (int a = 0; a < 16; a++) {
            #pragma unroll
            for (int o = 16; o; o >>= 1)
                part[a] += __shfl_xor_sync(0xFFFFFFFFu, part[a], o);
        }
        if (lane < 16) {
            float mysum = 0.f;
            #pragma unroll
            for (int a = 0; a < 16; a++) if (lane == a) mysum = part[a];
            sc += watt[p] * tanhf(mysum + bpf[p] + ps[pi]);
        }
    }
    if (lane < 16) atomicAdd(&g_score[b * AA + lane], sc);
}

// ---------------------------------------------------------------------------
__global__ void k_soft() {
    int b = blockIdx.x, lane = threadIdx.x;
    if (lane >= 16) return;
    float v = g_score[b * AA + lane];
    float m = v;
    #pragma unroll
    for (int o = 8; o; o >>= 1) m = fmaxf(m, __shfl_xor_sync(0xFFFFu, m, o));
    float e = expf(v - m);
    float sum = e;
    #pragma unroll
    for (int o = 8; o; o >>= 1) sum += __shfl_xor_sync(0xFFFFu, sum, o);
    g_attw[b * AA + lane] = e / sum;
}

// ---------------------------------------------------------------------------
__global__ void k_final(float* __restrict__ out) {
    __shared__ float aw[16];
    int b = blockIdx.x, tid = threadIdx.x;
    if (tid < 16) aw[tid] = g_attw[b * 16 + tid];
    __syncthreads();
    int hw = blockIdx.y * 256 + tid;
    if (hw < HWW) {
        const float* X = out + OFF_X + (size_t)b * AA * HWW;
        float s = 0.f;
        #pragma unroll
        for (int a = 0; a < 16; a++) s += X[a * HWW + hw] * aw[a];
        out[OFF_AX + b * HWW + hw] = s;
        out[OFF_Z + b * 1201 + 1 + hw] = s;
    }
    if (tid == 0 && blockIdx.y == 0) {
        float z = 0.f;
        #pragma unroll
        for (int a = 0; a < 16; a++) z += g_y[b * 16 + a] * aw[a];
        out[OFF_Z + b * 1201] = z;
    }
}

// ---------------------------------------------------------------------------
extern "C" void kernel_launch(void* const* d_in, const int* in_sizes, int n_in,
                              void* d_out, int out_size) {
    const float* enc  = (const float*)d_in[0];
    const float* feat = (const float*)d_in[1];
    const float* subj = (const float*)d_in[2];
    const float* w2   = (const float*)d_in[3];
    const float* b2   = (const float*)d_in[4];
    const float* w3   = (const float*)d_in[5];
    const float* b3   = (const float*)d_in[6];
    const float* wd1  = (const float*)d_in[7];
    const float* bd1  = (const float*)d_in[8];
    const float* wd2  = (const float*)d_in[9];
    const float* bd2  = (const float*)d_in[10];
    const float* wpf  = (const float*)d_in[11];
    const float* bpf  = (const float*)d_in[12];
    const float* wps  = (const float*)d_in[13];
    const float* bps  = (const float*)d_in[14];
    const float* watt = (const float*)d_in[15];
    float* out = (float*)d_out;

    k_zero<<<1024, 512>>>();
    k_x<<<dim3(64, 10), 128>>>(feat, w3, b3, out);
    k_drt1f<<<dim3(64, 8), 384>>>(feat, wd1);
    k_y<<<64, 512>>>(w2, b2);
    k_drt2<<<64, 64>>>(wd2, bd2, bd1, out);
    k_aggr<<<dim3(64, 4, 5), 128>>>(enc, out);
    k_score<<<dim3(64, 8), 256>>>(subj, wps, bps, wpf, bpf, watt);
    k_soft<<<64, 32>>>();
    k_final<<<dim3(64, 5), 256>>>(out);
}

// round 4
// speedup vs baseline: 2.2650x; 1.1331x over previous
#include <cuda_runtime.h>
#include <math.h>

#define BB  64
#define AA  16
#define CC  512
#define HH  30
#define WW  40
#define HWW 1200
#define EE  256
#define PP  512

#define OFF_Z  0
#define OFF_MU 76864
#define OFF_S2 76928
#define OFF_AX 76992
#define OFF_X  153792

// scratch: every element written each launch before being read (no zeroing needed)
__device__ float g_mean[BB * CC];
__device__ float g_y[BB * AA];
__device__ float g_t1p[8][BB * 48];
__device__ float g_scorep[8][BB * AA];
__device__ float g_aggrp[5][BB * AA * CC];

// stream + events created once at library load (host-side resources only)
static cudaStream_t g_s1;
static cudaEvent_t g_evFork, g_evJoin;
namespace {
struct InitStreams {
    InitStreams() {
        cudaStreamCreateWithFlags(&g_s1, cudaStreamNonBlocking);
        cudaEventCreateWithFlags(&g_evFork, cudaEventDisableTiming);
        cudaEventCreateWithFlags(&g_evJoin, cudaEventDisableTiming);
    }
};
InitStreams g_initStreams;
}

// ---------------------------------------------------------------------------
// x[b,a,hw] = relu(w_sal3[a,:] . F[b,:,hw] + b_sal3[a])
// grid (64, 10), block 128: one hw per thread, 16 a's in registers
__global__ void __launch_bounds__(128) k_x(const float* __restrict__ F,
                                           const float* __restrict__ w3,
                                           const float* __restrict__ b3,
                                           float* __restrict__ out) {
    __shared__ float ws[CC * AA];  // transposed [c][a]
    int b = blockIdx.x, tid = threadIdx.x;
    for (int i = tid; i < CC * AA; i += 128)
        ws[i] = w3[(i & 15) * CC + (i >> 4)];
    __syncthreads();

    int hw = blockIdx.y * 128 + tid;
    bool v = hw < HWW;
    int hwl = v ? hw : 0;
    const float* Fb = F + (size_t)b * CC * HWW + hwl;

    float acc[16];
    #pragma unroll
    for (int a = 0; a < 16; a++) acc[a] = 0.f;

    const float4* ws4 = (const float4*)ws;
    #pragma unroll 4
    for (int c = 0; c < CC; c++) {
        float f = Fb[c * HWW];
        #pragma unroll
        for (int a4 = 0; a4 < 4; a4++) {
            float4 w = ws4[c * 4 + a4];
            acc[a4 * 4 + 0] += w.x * f; acc[a4 * 4 + 1] += w.y * f;
            acc[a4 * 4 + 2] += w.z * f; acc[a4 * 4 + 3] += w.w * f;
        }
    }

    if (v) {
        float* X = out + OFF_X + (size_t)b * AA * HWW + hw;
        #pragma unroll
        for (int a = 0; a < 16; a++)
            X[a * HWW] = fmaxf(acc[a] + b3[a], 0.f);
    }
}

// ---------------------------------------------------------------------------
// Fused drt1 conv partials (bias+relu deferred) + per-channel mean of F.
// grid (64, 8), block 384, streams 64 channels of F through smem once.
__global__ void __launch_bounds__(384) k_drt1f(const float* __restrict__ F,
                                               const float* __restrict__ w1) {
    __shared__ float ch[2][HWW];
    __shared__ float wsh[64 * 49];
    __shared__ float csum[2][12];
    __shared__ float pos_acc[336];

    int b = blockIdx.x, c0 = blockIdx.y * 64;
    int tid = threadIdx.x;
    int wid = tid >> 5, lane = tid & 31;

    for (int i = tid; i < 64 * 49; i += 384) wsh[i] = w1[c0 * 49 + i];

    int pos = tid / 7, kh = tid - pos * 7;
    bool active = tid < 336;
    int oh = pos >> 3, ow = pos & 7;
    int ih = oh * 5 - 2 + kh;
    int iw0 = ow * 5 - 2;
    bool ihok = active && ih >= 0;

    const float* Fb = F + ((size_t)b * CC + c0) * HWW;

    {
        float ps = 0.f;
        if (tid < 300) {
            float4 v = ((const float4*)Fb)[tid];
            ((float4*)ch[0])[tid] = v;
            ps = v.x + v.y + v.z + v.w;
        }
        #pragma unroll
        for (int o = 16; o; o >>= 1) ps += __shfl_xor_sync(0xFFFFFFFFu, ps, o);
        if (!lane) csum[0][wid] = ps;
    }
    __syncthreads();

    float acc = 0.f;
    for (int c = 0; c < 64; c++) {
        int cur = c & 1;
        if (c < 63) {
            float ps = 0.f;
            if (tid < 300) {
                float4 v = ((const float4*)(Fb + (size_t)(c + 1) * HWW))[tid];
                ((float4*)ch[cur ^ 1])[tid] = v;
                ps = v.x + v.y + v.z + v.w;
            }
            #pragma unroll
            for (int o = 16; o; o >>= 1) ps += __shfl_xor_sync(0xFFFFFFFFu, ps, o);
            if (!lane) csum[cur ^ 1][wid] = ps;
        }
        if (tid == 0) {
            float m = 0.f;
            #pragma unroll
            for (int w = 0; w < 12; w++) m += csum[cur][w];
            g_mean[b * CC + c0 + c] = m * (1.f / HWW);
        }
        if (ihok) {
            const float* row = ch[cur] + ih * WW;
            const float* wr = wsh + c * 49 + kh * 7;
            #pragma unroll
            for (int kw = 0; kw < 7; kw++) {
                int iw = iw0 + kw;
                if (iw >= 0) acc += row[iw] * wr[kw];
            }
        }
        __syncthreads();
    }

    if (active) pos_acc[tid] = acc;
    __syncthreads();
    if (active && kh == 0) {
        float s = pos_acc[tid] + pos_acc[tid + 1] + pos_acc[tid + 2]
                + pos_acc[tid + 3] + pos_acc[tid + 4] + pos_acc[tid + 5]
                + pos_acc[tid + 6];
        g_t1p[blockIdx.y][b * 48 + pos] = s;
    }
}

// ---------------------------------------------------------------------------
// merged: y[b,a] dot + drt2 (bias1+relu on summed t1 partials, 6x8 conv, exp)
// grid 64, block 512
__global__ void __launch_bounds__(512) k_ydrt2(
    const float* __restrict__ w2, const float* __restrict__ b2,
    const float* __restrict__ wd2, const float* __restrict__ bd2,
    const float* __restrict__ bd1, float* __restrict__ out) {
    __shared__ float t1s[48];
    int b = blockIdx.x, tid = threadIdx.x;
    int a = tid >> 5, lane = tid & 31;

    if (tid < 48) {
        float t = 0.f;
        #pragma unroll
        for (int j = 0; j < 8; j++) t += g_t1p[j][b * 48 + tid];
        t1s[tid] = fmaxf(t + bd1[0], 0.f);
    }

    // y: warp per a
    const float4* m4 = (const float4*)(g_mean + b * CC);
    const float4* w4 = (const float4*)(w2 + a * CC);
    float s = 0.f;
    #pragma unroll
    for (int i = 0; i < 4; i++) {
        float4 mv = m4[lane + 32 * i];
        float4 wv = w4[lane + 32 * i];
        s += mv.x * wv.x + mv.y * wv.y + mv.z * wv.z + mv.w * wv.w;
    }
    #pragma unroll
    for (int o = 16; o; o >>= 1) s += __shfl_xor_sync(0xFFFFFFFFu, s, o);
    if (!lane) g_y[b * AA + a] = s + b2[a];

    __syncthreads();
    if (tid < 64) {
        int o = tid >> 5;
        float s2 = 0.f;
        for (int i = lane; i < 48; i += 32) s2 += t1s[i] * wd2[o * 48 + i];
        #pragma unroll
        for (int sh = 16; sh; sh >>= 1) s2 += __shfl_xor_sync(0xFFFFFFFFu, s2, sh);
        if (!lane) {
            float v = s2 + bd2[o];
            if (o == 0) out[OFF_MU + b] = v;
            else        out[OFF_S2 + b] = expf(v);
        }
    }
}

// ---------------------------------------------------------------------------
// aggr partial: grid (64, 2, 5), block 256, tile 256c x 16a, thread 4c x 4a
#define AK 24
#define AESTR 260
__global__ void __launch_bounds__(256) k_aggr(const float* __restrict__ Eenc,
                                              const float* __restrict__ out) {
    __shared__ float Esh[AK * AESTR];
    __shared__ float Xsh[AK * 16];
    int b = blockIdx.x;
    int c0 = blockIdx.y * 256;
    int z = blockIdx.z;
    int tid = threadIdx.x;
    int tc = tid & 63, ta = tid >> 6;

    const float* Eb = Eenc + ((size_t)b * CC + c0) * HWW;
    const float* Xb = out + OFF_X + (size_t)b * AA * HWW;

    float acc[4][4];
    #pragma unroll
    for (int i = 0; i < 4; i++)
        #pragma unroll
        for (int j = 0; j < 4; j++) acc[i][j] = 0.f;

    int hw0 = z * 240;
    for (int chunk = 0; chunk < 10; chunk++) {
        int k0 = hw0 + chunk * AK;
        // E: thread tid owns row c=tid, loads 24 floats as 6 float4
        const float4* Er = (const float4*)(Eb + (size_t)tid * HWW + k0);
        #pragma unroll
        for (int q = 0; q < 6; q++) {
            float4 v = Er[q];
            Esh[(q * 4 + 0) * AESTR + tid] = v.x;
            Esh[(q * 4 + 1) * AESTR + tid] = v.y;
            Esh[(q * 4 + 2) * AESTR + tid] = v.z;
            Esh[(q * 4 + 3) * AESTR + tid] = v.w;
        }
        if (tid < 96) {
            int aa = tid / 6, q = tid % 6;
            float4 v = *(const float4*)(Xb + aa * HWW + k0 + q * 4);
            Xsh[(q * 4 + 0) * 16 + aa] = v.x;
            Xsh[(q * 4 + 1) * 16 + aa] = v.y;
            Xsh[(q * 4 + 2) * 16 + aa] = v.z;
            Xsh[(q * 4 + 3) * 16 + aa] = v.w;
        }
        __syncthreads();
        #pragma unroll
        for (int k = 0; k < AK; k++) {
            float4 ev = *(const float4*)(Esh + k * AESTR + tc * 4);
            float4 xv = *(const float4*)(Xsh + k * 16 + ta * 4);
            acc[0][0] += xv.x * ev.x; acc[0][1] += xv.x * ev.y;
            acc[0][2] += xv.x * ev.z; acc[0][3] += xv.x * ev.w;
            acc[1][0] += xv.y * ev.x; acc[1][1] += xv.y * ev.y;
            acc[1][2] += xv.y * ev.z; acc[1][3] += xv.y * ev.w;
            acc[2][0] += xv.z * ev.x; acc[2][1] += xv.z * ev.y;
            acc[2][2] += xv.z * ev.z; acc[2][3] += xv.z * ev.w;
            acc[3][0] += xv.w * ev.x; acc[3][1] += xv.w * ev.y;
            acc[3][2] += xv.w * ev.z; acc[3][3] += xv.w * ev.w;
        }
        __syncthreads();
    }

    #pragma unroll
    for (int ia = 0; ia < 4; ia++) {
        float4 st;
        st.x = acc[ia][0] * (1.f / HWW);
        st.y = acc[ia][1] * (1.f / HWW);
        st.z = acc[ia][2] * (1.f / HWW);
        st.w = acc[ia][3] * (1.f / HWW);
        *(float4*)(g_aggrp[z] + ((size_t)b * AA + ta * 4 + ia) * CC + c0 + tc * 4) = st;
    }
}

// ---------------------------------------------------------------------------
// partial attention scores: grid (64, 8), block 256, 64 p's per block
__global__ void __launch_bounds__(256) k_score(
    const float* __restrict__ subj, const float* __restrict__ wps,
    const float* __restrict__ bps, const float* __restrict__ wpf,
    const float* __restrict__ bpf, const float* __restrict__ watt) {
    __shared__ float ssub[EE];
    __shared__ float ps[64];
    __shared__ float agg[AA * CC];
    __shared__ float scw[8][16];
    int b = blockIdx.x, p0 = blockIdx.y * 64;
    int tid = threadIdx.x;
    int wid = tid >> 5, lane = tid & 31;

    for (int i = tid; i < EE; i += 256) ssub[i] = subj[b * EE + i];
    for (int i = tid; i < AA * CC; i += 256) {
        float v = 0.f;
        #pragma unroll
        for (int z = 0; z < 5; z++) v += g_aggrp[z][(size_t)b * AA * CC + i];
        agg[i] = v;
    }
    __syncthreads();

    for (int pi = wid; pi < 64; pi += 8) {
        int p = p0 + pi;
        const float4* w4 = (const float4*)(wps + p * EE);
        const float4* s4 = (const float4*)ssub;
        float s = 0.f;
        #pragma unroll
        for (int i = 0; i < 2; i++) {
            float4 wv = w4[lane + 32 * i], sv = s4[lane + 32 * i];
            s += wv.x * sv.x + wv.y * sv.y + wv.z * sv.z + wv.w * sv.w;
        }
        #pragma unroll
        for (int o = 16; o; o >>= 1) s += __shfl_xor_sync(0xFFFFFFFFu, s, o);
        if (!lane) ps[pi] = s + bps[p];
    }
    __syncthreads();

    float sc = 0.f;
    const float4* agg4 = (const float4*)agg;
    for (int pi = wid; pi < 64; pi += 8) {
        int p = p0 + pi;
        const float4* w4 = (const float4*)(wpf + p * CC);
        float part[16];
        #pragma unroll
        for (int a = 0; a < 16; a++) part[a] = 0.f;
        #pragma unroll
        for (int j = 0; j < 4; j++) {
            float4 wv = w4[lane + 32 * j];
            #pragma unroll
            for (int a = 0; a < 16; a++) {
                float4 av = agg4[a * 128 + lane + 32 * j];
                part[a] += av.x * wv.x + av.y * wv.y + av.z * wv.z + av.w * wv.w;
            }
        }
        #pragma unroll
        for (int a = 0; a < 16; a++) {
            #pragma unroll
            for (int o = 16; o; o >>= 1)
                part[a] += __shfl_xor_sync(0xFFFFFFFFu, part[a], o);
        }
        if (lane < 16) {
            float mysum = 0.f;
            #pragma unroll
            for (int a = 0; a < 16; a++) if (lane == a) mysum = part[a];
            sc += watt[p] * tanhf(mysum + bpf[p] + ps[pi]);
        }
    }
    if (lane < 16) scw[wid][lane] = sc;
    __syncthreads();
    if (tid < 16) {
        float v = 0.f;
        #pragma unroll
        for (int j = 0; j < 8; j++) v += scw[j][tid];
        g_scorep[blockIdx.y][b * 16 + tid] = v;
    }
}

// ---------------------------------------------------------------------------
// softmax (redundant per block, 16 vals) + weighted sums.  grid (64,5), block 256
__global__ void k_final(float* __restrict__ out) {
    __shared__ float sc[16];
    __shared__ float aw[16];
    int b = blockIdx.x, tid = threadIdx.x;
    if (tid < 16) {
        float v = 0.f;
        #pragma unroll
        for (int j = 0; j < 8; j++) v += g_scorep[j][b * 16 + tid];
        sc[tid] = v;
    }
    __syncthreads();
    if (tid < 16) {
        float m = -1e30f;
        #pragma unroll
        for (int i = 0; i < 16; i++) m = fmaxf(m, sc[i]);
        float sum = 0.f;
        #pragma unroll
        for (int i = 0; i < 16; i++) sum += expf(sc[i] - m);
        aw[tid] = expf(sc[tid] - m) / sum;
    }
    __syncthreads();

    int hw = blockIdx.y * 256 + tid;
    if (hw < HWW) {
        const float* X = out + OFF_X + (size_t)b * AA * HWW;
        float s = 0.f;
        #pragma unroll
        for (int a = 0; a < 16; a++) s += X[a * HWW + hw] * aw[a];
        out[OFF_AX + b * HWW + hw] = s;
        out[OFF_Z + b * 1201 + 1 + hw] = s;
    }
    if (tid == 0 && blockIdx.y == 0) {
        float z = 0.f;
        #pragma unroll
        for (int a = 0; a < 16; a++) z += g_y[b * 16 + a] * aw[a];
        out[OFF_Z + b * 1201] = z;
    }
}

// ---------------------------------------------------------------------------
extern "C" void kernel_launch(void* const* d_in, const int* in_sizes, int n_in,
                              void* d_out, int out_size) {
    const float* enc  = (const float*)d_in[0];
    const float* feat = (const float*)d_in[1];
    const float* subj = (const float*)d_in[2];
    const float* w2   = (const float*)d_in[3];
    const float* b2   = (const float*)d_in[4];
    const float* w3   = (const float*)d_in[5];
    const float* b3   = (const float*)d_in[6];
    const float* wd1  = (const float*)d_in[7];
    const float* bd1  = (const float*)d_in[8];
    const float* wd2  = (const float*)d_in[9];
    const float* bd2  = (const float*)d_in[10];
    const float* wpf  = (const float*)d_in[11];
    const float* bpf  = (const float*)d_in[12];
    const float* wps  = (const float*)d_in[13];
    const float* bps  = (const float*)d_in[14];
    const float* watt = (const float*)d_in[15];
    float* out = (float*)d_out;

    // fork second stream off the capture stream
    cudaEventRecord(g_evFork, 0);
    cudaStreamWaitEvent(g_s1, g_evFork, 0);

    k_x<<<dim3(64, 10), 128>>>(feat, w3, b3, out);                 // 1 (s0)
    k_drt1f<<<dim3(64, 8), 384, 0, g_s1>>>(feat, wd1);             // 2 (s1)
    k_ydrt2<<<64, 512, 0, g_s1>>>(w2, b2, wd2, bd2, bd1, out);     // 3 (s1)
    k_aggr<<<dim3(64, 2, 5), 256>>>(enc, out);                     // 4 (s0) <- profiled
    k_score<<<dim3(64, 8), 256>>>(subj, wps, bps, wpf, bpf, watt); // 5 (s0)

    // join before k_final (needs g_y from s1)
    cudaEventRecord(g_evJoin, g_s1);
    cudaStreamWaitEvent(0, g_evJoin, 0);
    k_final<<<dim3(64, 5), 256>>>(out);                            // 6 (s0)
}